// round 2
// baseline (speedup 1.0000x reference)
#include <cuda_runtime.h>

// Problem constants (fixed for this problem instance)
#define NV 4096          // nodes per graph
#define BATCH 32         // batch size == warp width
#define NE 524288        // edges per graph
#define BN (NV * BATCH)  // 131072

// Scratch in transposed [node][batch] layout: node's 32 batch values = 128B line.
__device__ float g_xt[BN];
__device__ float g_fxt[BN];
__device__ float g_mut[BN];
__device__ float g_epst[BN];
__device__ float g_dxa[BN];

// Vector global reduction: 4 floats, 16B aligned. sm_90+ PTX.
__device__ __forceinline__ void red4(float* p, float a, float b, float c, float d) {
    asm volatile("red.relaxed.gpu.global.add.v4.f32 [%0], {%1,%2,%3,%4};"
                 :: "l"(p), "f"(a), "f"(b), "f"(c), "f"(d)
                 : "memory");
}

// K1: transpose x[B*N] -> xt[N*B], compute tanh, zero accumulators.
// grid: NV/32 blocks of (32,32). b = ty on load, tx on store.
__global__ void k_prep(const float* __restrict__ x) {
    __shared__ float s[32][33];
    int tx = threadIdx.x, ty = threadIdx.y, bx = blockIdx.x;
    // load: batch=ty, node=bx*32+tx  (coalesced over node)
    s[ty][tx] = x[ty * NV + bx * 32 + tx];
    __syncthreads();
    // store: node=bx*32+ty, batch=tx (coalesced over batch)
    int idx = (bx * 32 + ty) * BATCH + tx;
    float v = s[tx][ty];
    g_xt[idx]  = v;
    g_fxt[idx] = tanhf(v);
    g_mut[idx] = 0.0f;
    g_dxa[idx] = 0.0f;
}

// K2: mu[dst] += w * fx[src], batch-vectorized.
// Each group of 8 consecutive threads owns one edge; lane q covers batches 4q..4q+3.
__global__ void k_scatter_mu(const int* __restrict__ esrc, const int* __restrict__ edst,
                             const float* __restrict__ ew) {
    int t = blockIdx.x * blockDim.x + threadIdx.x;
    int q = t & 7;
    int g = t >> 3;
    int G = (gridDim.x * blockDim.x) >> 3;
    #pragma unroll 4
    for (int e = g; e < NE; e += G) {
        int s = esrc[e];
        int d = edst[e];
        float w = ew[e];
        float4 v = *(const float4*)(g_fxt + s * BATCH + q * 4);
        red4(g_mut + d * BATCH + q * 4, w * v.x, w * v.y, w * v.z, w * v.w);
    }
}

// K3: eps = x - mu (elementwise, vectorized)
__global__ void k_mid() {
    int i = blockIdx.x * blockDim.x + threadIdx.x;   // over BN/4
    float4 xv = ((const float4*)g_xt)[i];
    float4 mv = ((const float4*)g_mut)[i];
    float4 r;
    r.x = xv.x - mv.x; r.y = xv.y - mv.y; r.z = xv.z - mv.z; r.w = xv.w - mv.w;
    ((float4*)g_epst)[i] = r;
}

// K4: dxa[src] += w * eps[dst], batch-vectorized.
__global__ void k_scatter_dx(const int* __restrict__ esrc, const int* __restrict__ edst,
                             const float* __restrict__ ew) {
    int t = blockIdx.x * blockDim.x + threadIdx.x;
    int q = t & 7;
    int g = t >> 3;
    int G = (gridDim.x * blockDim.x) >> 3;
    #pragma unroll 4
    for (int e = g; e < NE; e += G) {
        int s = esrc[e];
        int d = edst[e];
        float w = ew[e];
        float4 v = *(const float4*)(g_epst + d * BATCH + q * 4);
        red4(g_dxa + s * BATCH + q * 4, w * v.x, w * v.y, w * v.z, w * v.w);
    }
}

// K5: dx = -eps + (1 - fx^2) * dxa; transpose both outputs back to [B*N].
__global__ void k_final(float* __restrict__ out) {
    __shared__ float smu[32][33];
    __shared__ float sdx[32][33];
    int tx = threadIdx.x, ty = threadIdx.y, bx = blockIdx.x;
    // read: node=bx*32+ty, batch=tx (coalesced)
    int idx = (bx * 32 + ty) * BATCH + tx;
    float mu = g_mut[idx];
    float ep = g_epst[idx];
    float fx = g_fxt[idx];
    float dx = -ep + (1.0f - fx * fx) * g_dxa[idx];
    smu[ty][tx] = mu;
    sdx[ty][tx] = dx;
    __syncthreads();
    // write: batch=ty, node=bx*32+tx (coalesced over node)
    int o = ty * NV + bx * 32 + tx;
    out[o]      = smu[tx][ty];
    out[BN + o] = sdx[tx][ty];
}

extern "C" void kernel_launch(void* const* d_in, const int* in_sizes, int n_in,
                              void* d_out, int out_size) {
    const float* x    = (const float*)d_in[0];
    const float* w    = (const float*)d_in[1];
    const int*   src  = (const int*)d_in[2];
    const int*   dst  = (const int*)d_in[3];
    float* out = (float*)d_out;

    dim3 t2(32, 32);
    k_prep<<<NV / 32, t2>>>(x);
    k_scatter_mu<<<1024, 256>>>(src, dst, w);
    k_mid<<<BN / 4 / 256, 256>>>();
    k_scatter_dx<<<1024, 256>>>(src, dst, w);
    k_final<<<NV / 32, t2>>>(out);
}